// round 2
// baseline (speedup 1.0000x reference)
#include <cuda_runtime.h>
#include <math.h>
#include <stdint.h>

// Problem constants (match reference setup_inputs)
#define BDIM      8
#define NTOK      8192
#define TOTT      (BDIM * NTOK)
#define NUMHEAVY  1024
#define NITERS    50

// Scratch (no cudaMalloc allowed)
__device__ float g_s[TOTT];
__device__ float g_inv[TOTT];                 // 32/||x_row|| (rmsnorm scale, gamma applied separately)
__device__ int   g_sel[BDIM * NUMHEAVY];
__device__ float g_hidden[33554432];          // max(65536*512, 8192*4096) floats = 128 MiB

// ---------------------------------------------------------------------------
// Kernel 1: per-token router logit s = x . routing_token and rmsnorm scale
// one warp per token
// ---------------------------------------------------------------------------
__global__ void dot_norm_kernel(const float* __restrict__ x,
                                const float* __restrict__ rt,
                                float* __restrict__ s_out,
                                float* __restrict__ inv_out,
                                int dim)
{
    int gwarp = (blockIdx.x * blockDim.x + threadIdx.x) >> 5;   // token id
    int lane  = threadIdx.x & 31;
    const float* xr = x + (size_t)gwarp * dim;
    float d = 0.f, q = 0.f;
    for (int k = lane; k < dim; k += 32) {
        float v = xr[k];
        d += v * rt[k];
        q += v * v;
    }
    #pragma unroll
    for (int o = 16; o; o >>= 1) {
        d += __shfl_xor_sync(0xffffffffu, d, o);
        q += __shfl_xor_sync(0xffffffffu, q, o);
    }
    if (lane == 0) {
        s_out[gwarp]   = d;
        float nrm = fmaxf(sqrtf(q), 1e-12f);
        inv_out[gwarp] = sqrtf((float)dim) / nrm;
    }
}

// ---------------------------------------------------------------------------
// Kernel 2: coor_descent (50 iters) + exact top-k with jax tie-breaking.
// One block (1024 threads) per batch row. Dynamic smem:
//   float ssh[NTOK] | uint64 keys[NTOK] | float red[32]
// ---------------------------------------------------------------------------
__global__ void router_kernel(const float* __restrict__ s_in,
                              float logk,
                              int* __restrict__ sel)
{
    extern __shared__ unsigned char smraw[];
    float* ssh = (float*)smraw;
    unsigned long long* keys = (unsigned long long*)(smraw + NTOK * sizeof(float));
    float* red = (float*)(smraw + NTOK * sizeof(float) + NTOK * sizeof(unsigned long long));

    const int tid = threadIdx.x;
    const int bt  = blockIdx.x;
    const int PER = NTOK / 1024;            // 8
    const float* srow = s_in + (size_t)bt * NTOK;

    for (int w = 0; w < PER; w++) ssh[tid + w * 1024] = srow[tid + w * 1024];
    __syncthreads();

    // iteration 1: s + b0 == 0 exactly -> logsumexp = log(n)
    float a = logk - logf((float)NTOK);

    for (int it = 1; it < NITERS; it++) {
        // arg_i = s_i - max(s_i + a, 0)   (== s + b, replicating jax fp ops)
        float args[8];
        float lm = -INFINITY;
        #pragma unroll
        for (int w = 0; w < 8; w++) {
            float sv = ssh[tid + w * 1024];
            float t  = sv + a;
            float ar = sv - fmaxf(t, 0.0f);
            args[w] = ar;
            lm = fmaxf(lm, ar);
        }
        #pragma unroll
        for (int o = 16; o; o >>= 1) lm = fmaxf(lm, __shfl_xor_sync(0xffffffffu, lm, o));
        if ((tid & 31) == 0) red[tid >> 5] = lm;
        __syncthreads();
        if (tid < 32) {
            float v = red[tid];
            #pragma unroll
            for (int o = 16; o; o >>= 1) v = fmaxf(v, __shfl_xor_sync(0xffffffffu, v, o));
            if (tid == 0) red[0] = v;
        }
        __syncthreads();
        float m = red[0];
        __syncthreads();                    // everyone read red[0] before reuse

        float ls = 0.f;
        #pragma unroll
        for (int w = 0; w < 8; w++) ls += expf(args[w] - m);
        #pragma unroll
        for (int o = 16; o; o >>= 1) ls += __shfl_xor_sync(0xffffffffu, ls, o);
        if ((tid & 31) == 0) red[tid >> 5] = ls;
        __syncthreads();
        if (tid < 32) {
            float v = red[tid];
            #pragma unroll
            for (int o = 16; o; o >>= 1) v += __shfl_xor_sync(0xffffffffu, v, o);
            if (tid == 0) red[0] = v;
        }
        __syncthreads();
        float ssum = red[0];
        __syncthreads();

        a = logk - (logf(ssum) + m);
    }

    // scores -> sort keys (descending score, ascending index == jax top_k order)
    #pragma unroll
    for (int w = 0; w < 8; w++) {
        int i = tid + w * 1024;
        float u  = ssh[i] + a;
        float sc = (u > 0.0f) ? 1.0f : expf(u);
        unsigned sb = __float_as_uint(sc) ^ 0xffffffffu;  // score >= 0 -> monotone
        keys[i] = ((unsigned long long)sb << 32) | (unsigned)i;
    }
    __syncthreads();

    // bitonic sort ascending over NTOK keys
    for (unsigned k = 2; k <= NTOK; k <<= 1) {
        for (unsigned j = k >> 1; j > 0; j >>= 1) {
            #pragma unroll
            for (int w = 0; w < 8; w++) {
                unsigned i  = tid + w * 1024;
                unsigned ix = i ^ j;
                if (ix > i) {
                    unsigned long long va = keys[i];
                    unsigned long long vb = keys[ix];
                    bool up = ((i & k) == 0);
                    if (up ? (va > vb) : (va < vb)) {
                        keys[i] = vb; keys[ix] = va;
                    }
                }
            }
            __syncthreads();
        }
    }

    if (tid < NUMHEAVY)
        sel[bt * NUMHEAVY + tid] = (int)(keys[tid] & 0xffffffffu);
}

// ---------------------------------------------------------------------------
// Fused GEMM: C[M,N] = act( A'[M,K] @ W[N,K]^T + bias )
// MODE 0: A = rmsnorm(x)*gamma (all tokens)    -> gelu -> hidden
// MODE 1: A = rmsnorm(x[sel])*gamma (gathered) -> gelu -> hidden
// MODE 2: A = hidden                           ->       C = v        (light out)
// MODE 3: A = hidden                           ->       C[sel] += v  (heavy scatter)
// 128x128 tile, 256 threads, 8x8 per thread, BK=8. All dims multiples of 128.
// ---------------------------------------------------------------------------
union F8 { float4 v[2]; float f[8]; };

template<int MODE>
__global__ __launch_bounds__(256)
void gemm_kernel(const float* __restrict__ Asrc,
                 const float* __restrict__ W,
                 const float* __restrict__ bias,
                 const float* __restrict__ scale,
                 const float* __restrict__ gamma,
                 const int*   __restrict__ sel,
                 float* __restrict__ C,
                 int M, int N, int K)
{
    __shared__ __align__(16) float As[8][128];
    __shared__ __align__(16) float Bs[8][128];
    __shared__ int   s_row[128];
    __shared__ float s_scl[128];
    __shared__ int   s_crow[128];

    const int tid = threadIdx.x;
    const int bx = blockIdx.x, by = blockIdx.y;

    if (tid < 128) {
        int m = by * 128 + tid;
        int arow = m; float sc = 1.0f; int crow = m;
        if (MODE == 0) {
            sc = scale[m];
        } else if (MODE == 1) {
            int t = sel[m];
            int g = (m >> 10) * NTOK + t;      // m/1024 = batch
            arow = g; sc = scale[g];
        } else if (MODE == 3) {
            int t = sel[m];
            crow = (m >> 10) * NTOK + t;
        }
        s_row[tid] = arow; s_scl[tid] = sc; s_crow[tid] = crow;
    }
    __syncthreads();

    float acc[8][8];
    #pragma unroll
    for (int i = 0; i < 8; i++)
        #pragma unroll
        for (int j = 0; j < 8; j++) acc[i][j] = 0.f;

    const int la_row = tid >> 1;          // 0..127
    const int la_k   = (tid & 1) * 4;     // 0 or 4
    const int tm0 = (tid >> 4) << 3;
    const int tn0 = (tid & 15) << 3;

    const size_t a_off = (size_t)s_row[la_row] * K + la_k;
    const float  a_s   = s_scl[la_row];
    const float* Wb = W + (size_t)(bx * 128 + la_row) * K + la_k;

    for (int k0 = 0; k0 < K; k0 += 8) {
        float4 av = *(const float4*)(Asrc + a_off + k0);
        if (MODE == 0 || MODE == 1) {
            float4 gv = *(const float4*)(gamma + k0 + la_k);
            av.x *= a_s * gv.x; av.y *= a_s * gv.y;
            av.z *= a_s * gv.z; av.w *= a_s * gv.w;
        }
        float4 wv = *(const float4*)(Wb + k0);
        As[la_k + 0][la_row] = av.x;
        As[la_k + 1][la_row] = av.y;
        As[la_k + 2][la_row] = av.z;
        As[la_k + 3][la_row] = av.w;
        Bs[la_k + 0][la_row] = wv.x;
        Bs[la_k + 1][la_row] = wv.y;
        Bs[la_k + 2][la_row] = wv.z;
        Bs[la_k + 3][la_row] = wv.w;
        __syncthreads();

        #pragma unroll
        for (int kk = 0; kk < 8; kk++) {
            F8 ar, br;
            ar.v[0] = *(const float4*)&As[kk][tm0];
            ar.v[1] = *(const float4*)&As[kk][tm0 + 4];
            br.v[0] = *(const float4*)&Bs[kk][tn0];
            br.v[1] = *(const float4*)&Bs[kk][tn0 + 4];
            #pragma unroll
            for (int i = 0; i < 8; i++)
                #pragma unroll
                for (int j = 0; j < 8; j++)
                    acc[i][j] += ar.f[i] * br.f[j];
        }
        __syncthreads();
    }

    #pragma unroll
    for (int i = 0; i < 8; i++) {
        int mloc = tm0 + i;
        #pragma unroll
        for (int j = 0; j < 8; j++) {
            int n = bx * 128 + tn0 + j;
            float v = acc[i][j] + bias[n];
            if (MODE == 0 || MODE == 1) {
                v = 0.5f * v * (1.0f + erff(v * 0.70710678118654752f));
                C[(size_t)(by * 128 + mloc) * N + n] = v;
            } else if (MODE == 2) {
                C[(size_t)(by * 128 + mloc) * N + n] = v;
            } else {
                size_t o = (size_t)s_crow[mloc] * N + n;
                C[o] += v;
            }
        }
    }
}

// ---------------------------------------------------------------------------
extern "C" void kernel_launch(void* const* d_in, const int* in_sizes, int n_in,
                              void* d_out, int out_size)
{
    const float* x       = (const float*)d_in[0];
    const float* rt      = (const float*)d_in[1];
    const float* gamma_l = (const float*)d_in[2];
    const float* w1_l    = (const float*)d_in[3];
    const float* b1_l    = (const float*)d_in[4];
    const float* w2_l    = (const float*)d_in[5];
    const float* b2_l    = (const float*)d_in[6];
    const float* gamma_h = (const float*)d_in[7];
    const float* w1_h    = (const float*)d_in[8];
    const float* b1_h    = (const float*)d_in[9];
    const float* w2_h    = (const float*)d_in[10];
    const float* b2_h    = (const float*)d_in[11];
    float* out = (float*)d_out;

    const int dim = in_sizes[1];   // 1024
    const int dl  = in_sizes[4];   // 512
    const int dh  = in_sizes[9];   // 4096

    float *p_s, *p_inv, *p_hid; int* p_sel;
    cudaGetSymbolAddress((void**)&p_s,   g_s);
    cudaGetSymbolAddress((void**)&p_inv, g_inv);
    cudaGetSymbolAddress((void**)&p_hid, g_hidden);
    cudaGetSymbolAddress((void**)&p_sel, g_sel);

    // 1. router logits + rmsnorm scales
    dot_norm_kernel<<<TOTT / 8, 256>>>(x, rt, p_s, p_inv, dim);

    // 2. coor_descent + top-k selection
    size_t smbytes = NTOK * sizeof(float) + NTOK * sizeof(unsigned long long) + 64 * sizeof(float);
    cudaFuncSetAttribute(router_kernel, cudaFuncAttributeMaxDynamicSharedMemorySize, (int)smbytes);
    float logk = logf(fminf((float)NUMHEAVY * (9.0f / 8.0f), (float)NTOK));
    router_kernel<<<BDIM, 1024, smbytes>>>(p_s, logk, p_sel);

    // 3. light FFN: gemm1+gelu -> hidden, gemm2 -> out
    {
        dim3 g1(dl / 128, TOTT / 128);
        gemm_kernel<0><<<g1, 256>>>(x, w1_l, b1_l, p_inv, gamma_l, nullptr, p_hid, TOTT, dl, dim);
        dim3 g2(dim / 128, TOTT / 128);
        gemm_kernel<2><<<g2, 256>>>(p_hid, w2_l, b2_l, nullptr, nullptr, nullptr, out, TOTT, dim, dl);
    }

    // 4. heavy FFN on gathered tokens: gemm1+gelu -> hidden (reuse), gemm2 scatter-add -> out
    {
        const int MH = BDIM * NUMHEAVY;            // 8192
        dim3 g1(dh / 128, MH / 128);
        gemm_kernel<1><<<g1, 256>>>(x, w1_h, b1_h, p_inv, gamma_h, p_sel, p_hid, MH, dh, dim);
        dim3 g2(dim / 128, MH / 128);
        gemm_kernel<3><<<g2, 256>>>(p_hid, w2_h, b2_h, nullptr, nullptr, p_sel, out, MH, dim, dh);
    }
}

// round 5
// speedup vs baseline: 1.9648x; 1.9648x over previous
#include <cuda_runtime.h>
#include <cuda_bf16.h>
#include <math.h>
#include <stdint.h>

#define BDIM 8
#define NTOK 8192
#define TOTT (BDIM*NTOK)
#define NUMHEAVY 1024
#define NITERS 50
#define MH (BDIM*NUMHEAVY)

typedef __nv_bfloat16 bf16;

// ---- scratch (__device__ globals; no allocs allowed) ----
__device__ float g_s[TOTT];
__device__ float g_inv[TOTT];
__device__ int   g_sel[MH];
__device__ bf16  g_xnh[TOTT*1024], g_xnl[TOTT*1024];
__device__ bf16  g_xgh[MH*1024],   g_xgl[MH*1024];
__device__ bf16  g_hh[33554432],   g_hl[33554432];
__device__ bf16  g_w1lh[512*1024],  g_w1ll[512*1024];
__device__ bf16  g_w2lh[1024*512],  g_w2ll[1024*512];
__device__ bf16  g_w1hh[4096*1024], g_w1hl[4096*1024];
__device__ bf16  g_w2hh[1024*4096], g_w2hl[1024*4096];

// ---- kernel 1: router logits + rmsnorm scales ----
__global__ void dot_norm_kernel(const float* __restrict__ x, const float* __restrict__ rt,
                                float* __restrict__ s_out, float* __restrict__ inv_out, int dim)
{
    int gw = (blockIdx.x*blockDim.x + threadIdx.x) >> 5;
    int lane = threadIdx.x & 31;
    const float* xr = x + (size_t)gw*dim;
    float d=0.f, q=0.f;
    for (int k=lane; k<dim; k+=32){ float v=xr[k]; d+=v*rt[k]; q+=v*v; }
    #pragma unroll
    for (int o=16;o;o>>=1){ d+=__shfl_xor_sync(~0u,d,o); q+=__shfl_xor_sync(~0u,q,o); }
    if (lane==0){ s_out[gw]=d; inv_out[gw]=sqrtf((float)dim)/fmaxf(sqrtf(q),1e-12f); }
}

// ---- kernel 2: coor_descent + exact top-k (jax-faithful, proven) ----
__global__ void router_kernel(const float* __restrict__ s_in, float logk, int* __restrict__ sel)
{
    extern __shared__ unsigned char smraw[];
    float* ssh = (float*)smraw;
    unsigned long long* keys = (unsigned long long*)(smraw + NTOK*4);
    float* red = (float*)(smraw + NTOK*4 + NTOK*8);
    const int tid = threadIdx.x, bt = blockIdx.x;
    const float* srow = s_in + (size_t)bt*NTOK;
    for (int w=0; w<8; w++) ssh[tid + w*1024] = srow[tid + w*1024];
    __syncthreads();

    float a = logk - logf((float)NTOK);
    for (int it=1; it<NITERS; it++){
        float args[8], lm=-INFINITY;
        #pragma unroll
        for (int w=0;w<8;w++){ float sv=ssh[tid+w*1024]; float ar=sv-fmaxf(sv+a,0.0f); args[w]=ar; lm=fmaxf(lm,ar); }
        #pragma unroll
        for (int o=16;o;o>>=1) lm=fmaxf(lm,__shfl_xor_sync(~0u,lm,o));
        if ((tid&31)==0) red[tid>>5]=lm;
        __syncthreads();
        if (tid<32){ float v=red[tid];
            #pragma unroll
            for (int o=16;o;o>>=1) v=fmaxf(v,__shfl_xor_sync(~0u,v,o));
            if (tid==0) red[0]=v; }
        __syncthreads();
        float m=red[0]; __syncthreads();
        float ls=0.f;
        #pragma unroll
        for (int w=0;w<8;w++) ls+=expf(args[w]-m);
        #pragma unroll
        for (int o=16;o;o>>=1) ls+=__shfl_xor_sync(~0u,ls,o);
        if ((tid&31)==0) red[tid>>5]=ls;
        __syncthreads();
        if (tid<32){ float v=red[tid];
            #pragma unroll
            for (int o=16;o;o>>=1) v+=__shfl_xor_sync(~0u,v,o);
            if (tid==0) red[0]=v; }
        __syncthreads();
        float ssum=red[0]; __syncthreads();
        a = logk - (logf(ssum)+m);
    }
    #pragma unroll
    for (int w=0;w<8;w++){
        int i=tid+w*1024;
        float u=ssh[i]+a;
        float sc=(u>0.0f)?1.0f:expf(u);
        unsigned sb=__float_as_uint(sc)^0xffffffffu;
        keys[i]=((unsigned long long)sb<<32)|(unsigned)i;
    }
    __syncthreads();
    for (unsigned k=2;k<=NTOK;k<<=1)
        for (unsigned j=k>>1;j>0;j>>=1){
            #pragma unroll
            for (int w=0;w<8;w++){
                unsigned i=tid+w*1024, ix=i^j;
                if (ix>i){
                    unsigned long long va=keys[i], vb=keys[ix];
                    bool up=((i&k)==0);
                    if (up ? (va>vb) : (va<vb)){ keys[i]=vb; keys[ix]=va; }
                }
            }
            __syncthreads();
        }
    if (tid<NUMHEAVY) sel[bt*NUMHEAVY+tid]=(int)(keys[tid]&0xffffffffu);
}

// ---- fp32 -> bf16 hi/lo split helpers ----
__device__ __forceinline__ void split4(float4 v, uint2& H, uint2& L){
    float f[4]={v.x,v.y,v.z,v.w}; unsigned h[4],l[4];
    #pragma unroll
    for (int i=0;i<4;i++){
        bf16 hb=__float2bfloat16_rn(f[i]);
        bf16 lb=__float2bfloat16_rn(f[i]-__bfloat162float(hb));
        h[i]=__bfloat16_as_ushort(hb); l[i]=__bfloat16_as_ushort(lb);
    }
    H.x=h[0]|(h[1]<<16); H.y=h[2]|(h[3]<<16);
    L.x=l[0]|(l[1]<<16); L.y=l[2]|(l[3]<<16);
}

__global__ void conv_plain(const float* __restrict__ s, bf16* __restrict__ dh, bf16* __restrict__ dl, int n4){
    int i = blockIdx.x*256 + threadIdx.x;
    if (i>=n4) return;
    uint2 H,L; split4(((const float4*)s)[i],H,L);
    ((uint2*)dh)[i]=H; ((uint2*)dl)[i]=L;
}

// rows*256 threads; one thread = 4 cols of one row. dim fixed 1024.
__global__ void conv_norm(const float* __restrict__ x, const float* __restrict__ inv,
                          const float* __restrict__ gamma, const int* __restrict__ sel,
                          bf16* __restrict__ dh, bf16* __restrict__ dl)
{
    int i = blockIdx.x*256 + threadIdx.x;
    int row = i>>8, c4 = (i&255)*4;
    int sr = row;
    if (sel) sr = (row>>10)*NTOK + sel[row];
    float sc = inv[sr];
    float4 v = *(const float4*)(x + (size_t)sr*1024 + c4);
    float4 g = *(const float4*)(gamma + c4);
    v.x*=sc*g.x; v.y*=sc*g.y; v.z*=sc*g.z; v.w*=sc*g.w;
    uint2 H,L; split4(v,H,L);
    *(uint2*)(dh + (size_t)row*1024 + c4)=H;
    *(uint2*)(dl + (size_t)row*1024 + c4)=L;
}

// ---- mma.sync bf16 GEMM core (compute_103-safe, runs on legacy HMMA path) ----
__device__ __forceinline__ uint32_t smem_u32(const void* p){
    uint32_t a;
    asm("{ .reg .u64 t; cvta.to.shared.u64 t, %1; cvt.u32.u64 %0, t; }":"=r"(a):"l"(p));
    return a;
}
__device__ __forceinline__ void cpa16(uint32_t dst, const void* src){
    asm volatile("cp.async.cg.shared.global [%0], [%1], 16;" :: "r"(dst), "l"(src));
}
__device__ __forceinline__ void cpa_commit(){ asm volatile("cp.async.commit_group;"); }
template<int N> __device__ __forceinline__ void cpa_wait(){ asm volatile("cp.async.wait_group %0;" :: "n"(N)); }

__device__ __forceinline__ void ldsm4(uint32_t* r, uint32_t addr){
    asm volatile("ldmatrix.sync.aligned.m8n8.x4.shared.b16 {%0,%1,%2,%3}, [%4];"
        : "=r"(r[0]),"=r"(r[1]),"=r"(r[2]),"=r"(r[3]) : "r"(addr));
}
__device__ __forceinline__ void mma_bf16(float* c, const uint32_t* a, const uint32_t* b){
    asm volatile("mma.sync.aligned.m16n8k16.row.col.f32.bf16.bf16.f32 "
        "{%0,%1,%2,%3}, {%4,%5,%6,%7}, {%8,%9}, {%0,%1,%2,%3};"
        : "+f"(c[0]),"+f"(c[1]),"+f"(c[2]),"+f"(c[3])
        : "r"(a[0]),"r"(a[1]),"r"(a[2]),"r"(a[3]), "r"(b[0]),"r"(b[1]));
}
// swizzled byte offset within a 128x64 bf16 tile (128B rows, 16B chunks)
__device__ __forceinline__ uint32_t toff(int row, int c){
    return (uint32_t)(row*128 + ((c ^ (row&7))*16));
}

// Tile: BM=128, BN=128, BK=64, 256 threads, 2-stage cp.async.
// C[M,N] = epi( (Ah+Al)@(Bh+Bl)^T + bias ), 3-term split.
// EPI 0: gelu -> Ch/Cl bf16 split   EPI 1: Cf = v   EPI 2: Cf[scatter_row] += v
#define STAGE_BYTES 65536
#define SMEM_T (2*STAGE_BYTES)
template<int EPI>
__global__ __launch_bounds__(256)
void tc_gemm(const bf16* __restrict__ Ah, const bf16* __restrict__ Al,
             const bf16* __restrict__ Bh, const bf16* __restrict__ Bl,
             const float* __restrict__ bias, const int* __restrict__ sel,
             float* __restrict__ Cf, bf16* __restrict__ Ch, bf16* __restrict__ Cl,
             int N, int K)
{
    extern __shared__ __align__(16) char dsm[];
    const uint32_t sb0 = smem_u32(dsm);
    const int tid = threadIdx.x;
    const int lane = tid & 31, warp = tid >> 5;
    const int wm = warp >> 2, wn = warp & 3;         // 2 x 4 warps
    const int bx = blockIdx.x, by = blockIdx.y;
    const int CH = K / 64;

    // ---- loader ----
    auto load_stage = [&](int s, int k0){
        uint32_t st = sb0 + s*STAGE_BYTES;
        const bf16* mats[4] = {Ah, Al, Bh, Bl};
        #pragma unroll
        for (int mat=0; mat<4; mat++){
            const bf16* Mp = mats[mat];
            int rbase = (mat<2) ? by*128 : bx*128;
            #pragma unroll
            for (int it=0; it<4; it++){
                int g = tid + it*256;
                int row = g>>3, c = g&7;
                cpa16(st + mat*16384 + toff(row,c),
                      Mp + (size_t)(rbase+row)*K + k0 + c*8);
            }
        }
        cpa_commit();
    };

    float acc[4][4][4];
    #pragma unroll
    for (int i=0;i<4;i++)
        #pragma unroll
        for (int j=0;j<4;j++)
            #pragma unroll
            for (int r=0;r<4;r++) acc[i][j][r]=0.f;

    // per-lane ldmatrix source coords
    const int a_r  = wm*64 + (lane & 15);        // + i*16
    const int a_ck = (lane >> 4);                // k8 half
    const int b_r  = wn*32 + (lane & 7) + ((lane >> 4) & 1)*8;  // + jp*16
    const int b_ck = (lane >> 3) & 1;

    load_stage(0, 0);

    for (int cIt=0; cIt<CH; cIt++){
        if (cIt+1 < CH) load_stage((cIt+1)&1, (cIt+1)*64);
        if (cIt+1 < CH) cpa_wait<1>(); else cpa_wait<0>();
        __syncthreads();

        uint32_t st = sb0 + (cIt&1)*STAGE_BYTES;
        #pragma unroll
        for (int ks=0; ks<4; ks++){
            uint32_t ah[4][4], al[4][4], bh[2][4], bl[2][4];
            #pragma unroll
            for (int i=0;i<4;i++){
                int row = a_r + i*16, c = ks*2 + a_ck;
                ldsm4(ah[i], st + toff(row,c));
                ldsm4(al[i], st + 16384 + toff(row,c));
            }
            #pragma unroll
            for (int jp=0;jp<2;jp++){
                int row = b_r + jp*16, c = ks*2 + b_ck;
                ldsm4(bh[jp], st + 32768 + toff(row,c));
                ldsm4(bl[jp], st + 49152 + toff(row,c));
            }
            #pragma unroll
            for (int i=0;i<4;i++)
                #pragma unroll
                for (int j=0;j<4;j++){
                    mma_bf16(acc[i][j], ah[i], &bh[j>>1][(j&1)*2]);   // AhBh
                    mma_bf16(acc[i][j], ah[i], &bl[j>>1][(j&1)*2]);   // AhBl
                    mma_bf16(acc[i][j], al[i], &bh[j>>1][(j&1)*2]);   // AlBh
                }
        }
        __syncthreads();
    }

    // ---- epilogue ----
    #pragma unroll
    for (int i=0;i<4;i++){
        #pragma unroll
        for (int half=0; half<2; half++){
            int m = by*128 + wm*64 + i*16 + (lane>>2) + half*8;
            size_t crow = (EPI==2) ? (size_t)((m>>10)*NTOK + sel[m]) : (size_t)m;
            #pragma unroll
            for (int j=0;j<4;j++){
                int n = bx*128 + wn*32 + j*8 + (lane&3)*2;
                float v0 = acc[i][j][half*2+0] + bias[n];
                float v1 = acc[i][j][half*2+1] + bias[n+1];
                if (EPI==0){
                    v0 = 0.5f*v0*(1.0f + erff(v0*0.70710678118654752f));
                    v1 = 0.5f*v1*(1.0f + erff(v1*0.70710678118654752f));
                    bf16 h0=__float2bfloat16_rn(v0), h1=__float2bfloat16_rn(v1);
                    bf16 l0=__float2bfloat16_rn(v0-__bfloat162float(h0));
                    bf16 l1=__float2bfloat16_rn(v1-__bfloat162float(h1));
                    unsigned hp = (unsigned)__bfloat16_as_ushort(h0) | ((unsigned)__bfloat16_as_ushort(h1)<<16);
                    unsigned lp = (unsigned)__bfloat16_as_ushort(l0) | ((unsigned)__bfloat16_as_ushort(l1)<<16);
                    *(unsigned*)(Ch + crow*(size_t)N + n) = hp;
                    *(unsigned*)(Cl + crow*(size_t)N + n) = lp;
                } else if (EPI==1){
                    float2 o; o.x=v0; o.y=v1;
                    *(float2*)(Cf + crow*(size_t)N + n) = o;
                } else {
                    float2* p = (float2*)(Cf + crow*(size_t)N + n);
                    float2 o = *p; o.x += v0; o.y += v1; *p = o;
                }
            }
        }
    }
}

// ---------------------------------------------------------------------------
extern "C" void kernel_launch(void* const* d_in, const int* in_sizes, int n_in,
                              void* d_out, int out_size)
{
    const float* x       = (const float*)d_in[0];
    const float* rt      = (const float*)d_in[1];
    const float* gamma_l = (const float*)d_in[2];
    const float* w1_l    = (const float*)d_in[3];
    const float* b1_l    = (const float*)d_in[4];
    const float* w2_l    = (const float*)d_in[5];
    const float* b2_l    = (const float*)d_in[6];
    const float* gamma_h = (const float*)d_in[7];
    const float* w1_h    = (const float*)d_in[8];
    const float* b1_h    = (const float*)d_in[9];
    const float* w2_h    = (const float*)d_in[10];
    const float* b2_h    = (const float*)d_in[11];
    float* out = (float*)d_out;

    const int dim = 1024, dl = 512, dh = 4096;

    float *p_s, *p_inv; int* p_sel;
    bf16 *xnh,*xnl,*xgh,*xgl,*hh,*hl,*w1lh,*w1ll,*w2lh,*w2ll,*w1hh,*w1hl,*w2hh,*w2hl;
    cudaGetSymbolAddress((void**)&p_s, g_s);
    cudaGetSymbolAddress((void**)&p_inv, g_inv);
    cudaGetSymbolAddress((void**)&p_sel, g_sel);
    cudaGetSymbolAddress((void**)&xnh, g_xnh);  cudaGetSymbolAddress((void**)&xnl, g_xnl);
    cudaGetSymbolAddress((void**)&xgh, g_xgh);  cudaGetSymbolAddress((void**)&xgl, g_xgl);
    cudaGetSymbolAddress((void**)&hh, g_hh);    cudaGetSymbolAddress((void**)&hl, g_hl);
    cudaGetSymbolAddress((void**)&w1lh, g_w1lh); cudaGetSymbolAddress((void**)&w1ll, g_w1ll);
    cudaGetSymbolAddress((void**)&w2lh, g_w2lh); cudaGetSymbolAddress((void**)&w2ll, g_w2ll);
    cudaGetSymbolAddress((void**)&w1hh, g_w1hh); cudaGetSymbolAddress((void**)&w1hl, g_w1hl);
    cudaGetSymbolAddress((void**)&w2hh, g_w2hh); cudaGetSymbolAddress((void**)&w2hl, g_w2hl);

    // router logits + rmsnorm scales
    dot_norm_kernel<<<TOTT/8, 256>>>(x, rt, p_s, p_inv, dim);

    // coor_descent + top-k
    size_t smb = NTOK*4 + NTOK*8 + 256;
    cudaFuncSetAttribute(router_kernel, cudaFuncAttributeMaxDynamicSharedMemorySize, (int)smb);
    float logk = logf(fminf((float)NUMHEAVY*(9.0f/8.0f), (float)NTOK));
    router_kernel<<<BDIM, 1024, smb>>>(p_s, logk, p_sel);

    // weight + activation conversions (split once)
    conv_plain<<<(dl*dim/4+255)/256, 256>>>(w1_l, w1lh, w1ll, dl*dim/4);
    conv_plain<<<(dim*dl/4+255)/256, 256>>>(w2_l, w2lh, w2ll, dim*dl/4);
    conv_plain<<<(dh*dim/4+255)/256, 256>>>(w1_h, w1hh, w1hl, dh*dim/4);
    conv_plain<<<(dim*dh/4+255)/256, 256>>>(w2_h, w2hh, w2hl, dim*dh/4);
    conv_norm<<<TOTT, 256>>>(x, p_inv, gamma_l, nullptr, xnh, xnl);
    conv_norm<<<MH, 256>>>(x, p_inv, gamma_h, p_sel, xgh, xgl);

    cudaFuncSetAttribute(tc_gemm<0>, cudaFuncAttributeMaxDynamicSharedMemorySize, SMEM_T);
    cudaFuncSetAttribute(tc_gemm<1>, cudaFuncAttributeMaxDynamicSharedMemorySize, SMEM_T);
    cudaFuncSetAttribute(tc_gemm<2>, cudaFuncAttributeMaxDynamicSharedMemorySize, SMEM_T);

    // light FFN
    {
        dim3 g1(dl/128, TOTT/128);
        tc_gemm<0><<<g1, 256, SMEM_T>>>(xnh, xnl, w1lh, w1ll, b1_l, nullptr, nullptr, hh, hl, dl, dim);
        dim3 g2(dim/128, TOTT/128);
        tc_gemm<1><<<g2, 256, SMEM_T>>>(hh, hl, w2lh, w2ll, b2_l, nullptr, out, nullptr, nullptr, dim, dl);
    }
    // heavy FFN (gathered) + scatter-add
    {
        dim3 g1(dh/128, MH/128);
        tc_gemm<0><<<g1, 256, SMEM_T>>>(xgh, xgl, w1hh, w1hl, b1_h, nullptr, nullptr, hh, hl, dh, dim);
        dim3 g2(dim/128, MH/128);
        tc_gemm<2><<<g2, 256, SMEM_T>>>(hh, hl, w2hh, w2hl, b2_h, p_sel, out, nullptr, nullptr, dim, dh);
    }
}